// round 14
// baseline (speedup 1.0000x reference)
#include <cuda_runtime.h>
#include <math_constants.h>
#include <cstdint>

#define NBATCH    512
#define NTOKS     512
#define DIN       128
#define TOPK_N    12
#define NTHREADS  256

// global scratch (contiguous per tensor for coalesced K2 loads)
__device__ float4 g_k[NBATCH * NTOKS];   // pre-scaled k
__device__ float4 g_q[NBATCH * NTOKS];

// ---------- PTX helpers ----------
__device__ __forceinline__ float ex2f_fast(float x) {
    float r; asm("ex2.approx.f32 %0, %1;" : "=f"(r) : "f"(x)); return r;
}
__device__ __forceinline__ float rcpf_fast(float x) {
    float r; asm("rcp.approx.f32 %0, %1;" : "=f"(r) : "f"(x)); return r;
}
__device__ __forceinline__ unsigned long long pk2(float lo, float hi) {
    unsigned long long r; asm("mov.b64 %0, {%1, %2};" : "=l"(r) : "f"(lo), "f"(hi)); return r;
}
__device__ __forceinline__ void upk2(float& lo, float& hi, unsigned long long v) {
    asm("mov.b64 {%0, %1}, %2;" : "=f"(lo), "=f"(hi) : "l"(v));
}
__device__ __forceinline__ unsigned long long fma2(unsigned long long a,
                                                   unsigned long long b,
                                                   unsigned long long c) {
    unsigned long long r;
    asm("fma.rn.f32x2 %0, %1, %2, %3;" : "=l"(r) : "l"(a), "l"(b), "l"(c));
    return r;
}
__device__ __forceinline__ unsigned long long add2(unsigned long long a,
                                                   unsigned long long b) {
    unsigned long long r;
    asm("add.rn.f32x2 %0, %1, %2;" : "=l"(r) : "l"(a), "l"(b));
    return r;
}
__device__ __forceinline__ void cp_async16(uint32_t saddr, const void* gaddr) {
    asm volatile("cp.async.cg.shared.global [%0], [%1], 16;" :: "r"(saddr), "l"(gaddr));
}
// order-preserving float<->uint key (all finite floats incl. negatives)
__device__ __forceinline__ unsigned fkey(float v) {
    int b = __float_as_int(v);
    return (unsigned)b ^ (unsigned)((b >> 31) | 0x80000000);
}
__device__ __forceinline__ float funkey(unsigned k) {
    int b = (k & 0x80000000u) ? (int)(k ^ 0x80000000u) : ~(int)k;
    return __int_as_float(b);
}
// exact true warp max (handles negative floats, unlike raw s32 REDUX)
__device__ __forceinline__ float redux_maxf(float v) {
    return funkey(__reduce_max_sync(0xffffffffu, fkey(v)));
}
// exact-to-2^-26 warp sum of nonneg per-lane partials <= 16. REQUIRES the
// true-rowmax shift (max arg == 0 -> s >= 1); with a floored shift s can be
// << 2^-26 and this underflows to 0 -> rcp(0)=inf (round-12 bug).
__device__ __forceinline__ float redux_sum_pos(float partial) {
    unsigned u = __float2uint_rn(partial * 67108864.0f);      // * 2^26, <= 2^30
    unsigned losum = __reduce_add_sync(0xffffffffu, u & 0xFFFFu);
    unsigned hisum = __reduce_add_sync(0xffffffffu, u >> 16);
    return fmaf((float)hisum, 65536.0f, (float)losum) * 1.490116119384765625e-8f; // 2^-26
}

// ======================= K1: projection (unchanged, proven) =================
// grid (8, 512) = (chunk of 64 tokens, batch); 256 threads
__global__ __launch_bounds__(NTHREADS)
void proj_kernel(const float* __restrict__ x,
                 const float* __restrict__ wk,
                 const float* __restrict__ wq)
{
    __shared__ float xs[64 * 132];        // 528B token stride, conflict-free
    __shared__ float wks[512], wqs[512];
    __shared__ float4 sc4[128];

    const int tid = threadIdx.x;
    const int c = blockIdx.x;
    const int b = blockIdx.y;
    const float4* xg4 = (const float4*)(x + ((size_t)b * NTOKS + (size_t)c * 64) * DIN);

    for (int i = tid; i < 512; i += NTHREADS) { wks[i] = wk[i]; wqs[i] = wq[i]; }

    uint32_t xs_s = (uint32_t)__cvta_generic_to_shared(xs);
    #pragma unroll
    for (int k2 = 0; k2 < 8; ++k2) {
        int idx = tid + k2 * NTHREADS;          // 0..2047
        int t = idx >> 5, e4 = idx & 31;
        cp_async16(xs_s + (uint32_t)(t * 132 + e4 * 4) * 4u, xg4 + idx);
    }
    asm volatile("cp.async.commit_group;");
    asm volatile("cp.async.wait_group 0;");
    __syncthreads();

    const int token = tid & 63;
    const int dhalf = (tid >> 6) & 1;
    const int proj  = tid >> 7;
    const float4* wsel4 = (const float4*)(proj ? wqs : wks);
    const float4* xr = (const float4*)(xs + token * 132 + dhalf * 64);

    float a0 = 0.f, a1 = 0.f, a2 = 0.f, a3 = 0.f;
    #pragma unroll
    for (int i = 0; i < 16; ++i) {
        float4 xv = xr[i];
        int e4 = dhalf * 16 + i;
        float4 w0 = wsel4[e4 * 4 + 0];
        float4 w1 = wsel4[e4 * 4 + 1];
        float4 w2 = wsel4[e4 * 4 + 2];
        float4 w3 = wsel4[e4 * 4 + 3];
        a0 = fmaf(xv.x, w0.x, a0); a1 = fmaf(xv.x, w0.y, a1);
        a2 = fmaf(xv.x, w0.z, a2); a3 = fmaf(xv.x, w0.w, a3);
        a0 = fmaf(xv.y, w1.x, a0); a1 = fmaf(xv.y, w1.y, a1);
        a2 = fmaf(xv.y, w1.z, a2); a3 = fmaf(xv.y, w1.w, a3);
        a0 = fmaf(xv.z, w2.x, a0); a1 = fmaf(xv.z, w2.y, a1);
        a2 = fmaf(xv.z, w2.z, a2); a3 = fmaf(xv.z, w2.w, a3);
        a0 = fmaf(xv.w, w3.x, a0); a1 = fmaf(xv.w, w3.y, a1);
        a2 = fmaf(xv.w, w3.z, a2); a3 = fmaf(xv.w, w3.w, a3);
    }
    if (dhalf) sc4[proj * 64 + token] = make_float4(a0, a1, a2, a3);
    __syncthreads();
    if (!dhalf) {
        float4 p = sc4[proj * 64 + token];
        a0 += p.x; a1 += p.y; a2 += p.z; a3 += p.w;
        // (1/sqrt(128)) * log2(e) folded into k
        const float KSCALE = 0.0883883476483184405f * 1.4426950408889634074f;
        size_t o = (size_t)b * NTOKS + (size_t)c * 64 + token;
        if (proj == 0)
            g_k[o] = make_float4(a0 * KSCALE, a1 * KSCALE, a2 * KSCALE, a3 * KSCALE);
        else
            g_q[o] = make_float4(a0, a1, a2, a3);
    }
}

// ======================= K2: scores + softmax-sum + topk + gather ===========
// Round-4 numerics (TRUE rowmax via fkey REDUX + fixed-point REDUX sum, both
// proven rel_err=0 together) on the round-10 structure (Q in smem, 4 CTAs/SM)
// plus kdup (pre-duplicated packed k rows -> broadcast LDS.128).
__global__ __launch_bounds__(NTHREADS, 4)
void attn_kernel(const float* __restrict__ x, float* __restrict__ out)
{
    // kdup2[row*2+0] = {(kx,kx),(ky,ky)}, [row*2+1] = {(kz,kz),(kw,kw)}  (16 KB)
    __shared__ ulonglong2 kdup2[NTOKS * 2];
    // qp2[pair p][lane]: .x = Q slot 2p, .y = slot 2p+1 (p = 0..15). Lane
    // stride 16B -> 4-phase conflict-free LDS.128 / STS.128. (8 KB)
    __shared__ ulonglong2 qp2[16 * 32];
    __shared__ float Ash[NTOKS];
    __shared__ int sel[16];

    const int tid  = threadIdx.x;
    const int lane = tid & 31;
    const int warp = tid >> 5;
    const int b    = blockIdx.x;
    const float4* kg = g_k + (size_t)b * NTOKS;
    const float4* qg = g_q + (size_t)b * NTOKS;

    // load k (coalesced) and build duplicated packed rows
    #pragma unroll
    for (int it = 0; it < 2; ++it) {
        int t = tid + it * NTHREADS;
        float4 kv = kg[t];
        ulonglong2 lo, hi;
        lo.x = pk2(kv.x, kv.x); lo.y = pk2(kv.y, kv.y);
        hi.x = pk2(kv.z, kv.z); hi.y = pk2(kv.w, kv.w);
        kdup2[t * 2]     = lo;
        kdup2[t * 2 + 1] = hi;
    }
    // load + pack q. Thread (i = tid>>5, ln): lane ln owns cols ln+32j;
    // slot 4i+c packs (col ln+64i, col ln+64i+32) component c.
    {
        int i = tid >> 5, ln = tid & 31;
        int m = ln + 64 * i;
        float4 qa = qg[m];
        float4 qb = qg[m + 32];
        ulonglong2 lo, hi;
        lo.x = pk2(qa.x, qb.x);  lo.y = pk2(qa.y, qb.y);   // slots 4i, 4i+1
        hi.x = pk2(qa.z, qb.z);  hi.y = pk2(qa.w, qb.w);   // slots 4i+2, 4i+3
        qp2[(2 * i) * 32 + ln]     = lo;
        qp2[(2 * i + 1) * 32 + ln] = hi;
    }
    for (int i = tid; i < NTOKS; i += NTHREADS) Ash[i] = 0.f;
    __syncthreads();

    const unsigned long long BIAS = pk2(-100.0f, -100.0f);

    unsigned long long A2[8];
    #pragma unroll
    for (int i = 0; i < 8; ++i) A2[i] = 0ull;

    #pragma unroll 1
    for (int rp = 0; rp < 32; ++rp) {
        int n = warp * 64 + rp * 2;
        ulonglong2 kaL = kdup2[n * 2];          // broadcast LDS.128
        ulonglong2 kaH = kdup2[n * 2 + 1];
        ulonglong2 kbL = kdup2[n * 2 + 2];
        ulonglong2 kbH = kdup2[n * 2 + 3];

        // dots with -100 bias folded into the accumulator init; Q from smem
        unsigned long long e0[8], e1[8];
        #pragma unroll
        for (int i = 0; i < 8; ++i) {
            ulonglong2 qA = qp2[(2 * i) * 32 + lane];       // slots 4i, 4i+1
            ulonglong2 qB = qp2[(2 * i + 1) * 32 + lane];   // slots 4i+2, 4i+3
            unsigned long long a  = fma2(qA.x, kaL.x, BIAS);
            unsigned long long bb = fma2(qA.x, kbL.x, BIAS);
            a  = fma2(qA.y, kaL.y, a);  bb = fma2(qA.y, kbL.y, bb);
            a  = fma2(qB.x, kaH.x, a);  bb = fma2(qB.x, kbH.x, bb);
            a  = fma2(qB.y, kaH.y, a);  bb = fma2(qB.y, kbH.y, bb);
            e0[i] = a; e1[i] = bb;
        }

        // TRUE row max (exact, sign-safe): fmaxf tree + fkey REDUX.
        // Max arg becomes exactly 0 after the shift -> e_max = 1, s >= 1,
        // which the fixed-point sum below requires.
        float m0 = -CUDART_INF_F, m1 = -CUDART_INF_F;
        #pragma unroll
        for (int i = 0; i < 8; ++i) {
            float lo, hi;
            upk2(lo, hi, e0[i]); m0 = fmaxf(m0, fmaxf(lo, hi));
            upk2(lo, hi, e1[i]); m1 = fmaxf(m1, fmaxf(lo, hi));
        }
        m0 = redux_maxf(m0);
        m1 = redux_maxf(m1);

        // subtract shift (packed), exp2: args <= 0 -> e <= 1 always
        unsigned long long S0 = pk2(-m0, -m0), S1 = pk2(-m1, -m1);
        #pragma unroll
        for (int i = 0; i < 8; ++i) {
            float lo, hi;
            upk2(lo, hi, add2(e0[i], S0));
            e0[i] = pk2(ex2f_fast(lo), ex2f_fast(hi));
            upk2(lo, hi, add2(e1[i], S1));
            e1[i] = pk2(ex2f_fast(lo), ex2f_fast(hi));
        }

        // packed lane-sum trees, then shfl-free fixed-point REDUX warp sum
        unsigned long long t0 = add2(add2(add2(e0[0], e0[1]), add2(e0[2], e0[3])),
                                     add2(add2(e0[4], e0[5]), add2(e0[6], e0[7])));
        unsigned long long t1 = add2(add2(add2(e1[0], e1[1]), add2(e1[2], e1[3])),
                                     add2(add2(e1[4], e1[5]), add2(e1[6], e1[7])));
        float lo, hi;
        upk2(lo, hi, t0); float s0 = lo + hi;     // in [0,16], row total >= 1
        upk2(lo, hi, t1); float s1 = lo + hi;
        s0 = redux_sum_pos(s0);
        s1 = redux_sum_pos(s1);

        unsigned long long v0, v1;
        {
            float i0 = rcpf_fast(s0), i1 = rcpf_fast(s1);
            v0 = pk2(i0, i0); v1 = pk2(i1, i1);
        }
        #pragma unroll
        for (int i = 0; i < 8; ++i) {
            A2[i] = fma2(e0[i], v0, A2[i]);
            A2[i] = fma2(e1[i], v1, A2[i]);
        }
    }

    #pragma unroll
    for (int i = 0; i < 8; ++i) {
        float lo, hi;
        upk2(lo, hi, A2[i]);
        atomicAdd(&Ash[lane + 64 * i], lo);
        atomicAdd(&Ash[lane + 64 * i + 32], hi);
    }
    __syncthreads();

    // top-12: JAX order (descending, ties -> lower index)
    if (warp == 0) {
        float av[16];
        #pragma unroll
        for (int j = 0; j < 16; ++j) av[j] = Ash[lane + 32 * j];
        #pragma unroll 1
        for (int t = 0; t < TOPK_N; ++t) {
            float bv = -CUDART_INF_F;
            int   bi = 0x7fffffff;
            #pragma unroll
            for (int j = 0; j < 16; ++j) {
                float v = av[j];
                if (v > bv) { bv = v; bi = lane + 32 * j; }
            }
            unsigned key = fkey(bv);
            unsigned win = __reduce_max_sync(0xffffffffu, key);
            unsigned cand = (key == win) ? (unsigned)bi : 0x7fffffffu;
            int idx = (int)__reduce_min_sync(0xffffffffu, cand);
            if (lane == 0) sel[t] = idx;
            #pragma unroll
            for (int j = 0; j < 16; ++j)
                if (idx == lane + 32 * j) av[j] = -CUDART_INF_F;
        }
    }
    __syncthreads();

    const float4* xb4 = (const float4*)(x + (size_t)b * NTOKS * DIN);
    float4* ob4 = (float4*)(out + (size_t)b * TOPK_N * DIN);
    for (int i = tid; i < TOPK_N * 32; i += NTHREADS) {
        int t  = i >> 5;
        int e4 = i & 31;
        ob4[i] = xb4[sel[t] * 32 + e4];
    }
}

extern "C" void kernel_launch(void* const* d_in, const int* in_sizes, int n_in,
                              void* d_out, int out_size)
{
    const float* x  = (const float*)d_in[0];
    const float* wk = (const float*)d_in[1];
    const float* wq = (const float*)d_in[2];
    float* out = (float*)d_out;
    (void)in_sizes; (void)n_in; (void)out_size;

    dim3 g1(8, NBATCH);
    proj_kernel<<<g1, NTHREADS>>>(x, wk, wq);
    attn_kernel<<<NBATCH, NTHREADS>>>(x, out);
}

// round 15
// speedup vs baseline: 1.7594x; 1.7594x over previous
#include <cuda_runtime.h>
#include <math_constants.h>
#include <cstdint>

#define NBATCH    512
#define NTOKS     512
#define DIN       128
#define TOPK_N    12
#define NTHREADS  256

// global scratch (contiguous per tensor for coalesced K2 loads)
__device__ float4 g_k[NBATCH * NTOKS];   // pre-scaled k
__device__ float4 g_q[NBATCH * NTOKS];

// ---------- PTX helpers ----------
__device__ __forceinline__ float ex2f_fast(float x) {
    float r; asm("ex2.approx.f32 %0, %1;" : "=f"(r) : "f"(x)); return r;
}
__device__ __forceinline__ float rcpf_fast(float x) {
    float r; asm("rcp.approx.f32 %0, %1;" : "=f"(r) : "f"(x)); return r;
}
__device__ __forceinline__ unsigned long long pk2(float lo, float hi) {
    unsigned long long r; asm("mov.b64 %0, {%1, %2};" : "=l"(r) : "f"(lo), "f"(hi)); return r;
}
__device__ __forceinline__ void upk2(float& lo, float& hi, unsigned long long v) {
    asm("mov.b64 {%0, %1}, %2;" : "=f"(lo), "=f"(hi) : "l"(v));
}
__device__ __forceinline__ unsigned long long fma2(unsigned long long a,
                                                   unsigned long long b,
                                                   unsigned long long c) {
    unsigned long long r;
    asm("fma.rn.f32x2 %0, %1, %2, %3;" : "=l"(r) : "l"(a), "l"(b), "l"(c));
    return r;
}
__device__ __forceinline__ unsigned long long add2(unsigned long long a,
                                                   unsigned long long b) {
    unsigned long long r;
    asm("add.rn.f32x2 %0, %1, %2;" : "=l"(r) : "l"(a), "l"(b));
    return r;
}
__device__ __forceinline__ void cp_async16(uint32_t saddr, const void* gaddr) {
    asm volatile("cp.async.cg.shared.global [%0], [%1], 16;" :: "r"(saddr), "l"(gaddr));
}
__device__ __forceinline__ unsigned fkey(float v) {
    int b = __float_as_int(v);
    return (unsigned)b ^ (unsigned)((b >> 31) | 0x80000000);
}

// ======================= K1: projection (unchanged, proven) =================
// grid (8, 512) = (chunk of 64 tokens, batch); 256 threads
__global__ __launch_bounds__(NTHREADS)
void proj_kernel(const float* __restrict__ x,
                 const float* __restrict__ wk,
                 const float* __restrict__ wq)
{
    __shared__ float xs[64 * 132];        // 528B token stride, conflict-free
    __shared__ float wks[512], wqs[512];
    __shared__ float4 sc4[128];

    const int tid = threadIdx.x;
    const int c = blockIdx.x;
    const int b = blockIdx.y;
    const float4* xg4 = (const float4*)(x + ((size_t)b * NTOKS + (size_t)c * 64) * DIN);

    for (int i = tid; i < 512; i += NTHREADS) { wks[i] = wk[i]; wqs[i] = wq[i]; }

    uint32_t xs_s = (uint32_t)__cvta_generic_to_shared(xs);
    #pragma unroll
    for (int k2 = 0; k2 < 8; ++k2) {
        int idx = tid + k2 * NTHREADS;          // 0..2047
        int t = idx >> 5, e4 = idx & 31;
        cp_async16(xs_s + (uint32_t)(t * 132 + e4 * 4) * 4u, xg4 + idx);
    }
    asm volatile("cp.async.commit_group;");
    asm volatile("cp.async.wait_group 0;");
    __syncthreads();

    const int token = tid & 63;
    const int dhalf = (tid >> 6) & 1;
    const int proj  = tid >> 7;
    const float4* wsel4 = (const float4*)(proj ? wqs : wks);
    const float4* xr = (const float4*)(xs + token * 132 + dhalf * 64);

    float a0 = 0.f, a1 = 0.f, a2 = 0.f, a3 = 0.f;
    #pragma unroll
    for (int i = 0; i < 16; ++i) {
        float4 xv = xr[i];
        int e4 = dhalf * 16 + i;
        float4 w0 = wsel4[e4 * 4 + 0];
        float4 w1 = wsel4[e4 * 4 + 1];
        float4 w2 = wsel4[e4 * 4 + 2];
        float4 w3 = wsel4[e4 * 4 + 3];
        a0 = fmaf(xv.x, w0.x, a0); a1 = fmaf(xv.x, w0.y, a1);
        a2 = fmaf(xv.x, w0.z, a2); a3 = fmaf(xv.x, w0.w, a3);
        a0 = fmaf(xv.y, w1.x, a0); a1 = fmaf(xv.y, w1.y, a1);
        a2 = fmaf(xv.y, w1.z, a2); a3 = fmaf(xv.y, w1.w, a3);
        a0 = fmaf(xv.z, w2.x, a0); a1 = fmaf(xv.z, w2.y, a1);
        a2 = fmaf(xv.z, w2.z, a2); a3 = fmaf(xv.z, w2.w, a3);
        a0 = fmaf(xv.w, w3.x, a0); a1 = fmaf(xv.w, w3.y, a1);
        a2 = fmaf(xv.w, w3.z, a2); a3 = fmaf(xv.w, w3.w, a3);
    }
    if (dhalf) sc4[proj * 64 + token] = make_float4(a0, a1, a2, a3);
    __syncthreads();
    if (!dhalf) {
        float4 p = sc4[proj * 64 + token];
        a0 += p.x; a1 += p.y; a2 += p.z; a3 += p.w;
        // (1/sqrt(128)) * log2(e) folded into k
        const float KSCALE = 0.0883883476483184405f * 1.4426950408889634074f;
        size_t o = (size_t)b * NTOKS + (size_t)c * 64 + token;
        if (proj == 0)
            g_k[o] = make_float4(a0 * KSCALE, a1 * KSCALE, a2 * KSCALE, a3 * KSCALE);
        else
            g_q[o] = make_float4(a0, a1, a2, a3);
    }
}

// ======================= K2: scores + softmax-sum + topk + gather ===========
// Exactly the round-10 proven kernel (78us, rel_err 0, NO spills: 64 regs)
// plus ONE register-reducing trim: kdup (k rows pre-duplicated/packed in
// smem; 4 direct ulonglong2 broadcast loads replace float4 loads + 8 pk2
// MOV-pair builds per pair). Softmax machinery untouched from R10:
// seeded-0 fmaxf tree + raw s32 REDUX.MAX (exact: all values >= 0), packed
// f32x2 butterfly warp sum (safe for any s). Round 14's fkey-max +
// fixed-point-sum combo is reverted: its extra temporaries spilled e0/e1 to
// local memory (L2 1.3% -> 49.2%) and cost 2.3x.
__global__ __launch_bounds__(NTHREADS, 4)
void attn_kernel(const float* __restrict__ x, float* __restrict__ out)
{
    // kdup2[row*2+0] = {(kx,kx),(ky,ky)}, [row*2+1] = {(kz,kz),(kw,kw)}  (16 KB)
    __shared__ ulonglong2 kdup2[NTOKS * 2];
    // qp2[pair p][lane]: .x = Q slot 2p, .y = slot 2p+1 (p = 0..15). Lane
    // stride 16B -> 4-phase conflict-free LDS.128 / STS.128. (8 KB)
    __shared__ ulonglong2 qp2[16 * 32];
    __shared__ float Ash[NTOKS];
    __shared__ int sel[16];

    const int tid  = threadIdx.x;
    const int lane = tid & 31;
    const int warp = tid >> 5;
    const int b    = blockIdx.x;
    const float4* kg = g_k + (size_t)b * NTOKS;
    const float4* qg = g_q + (size_t)b * NTOKS;

    // load k (coalesced) and build duplicated packed rows
    #pragma unroll
    for (int it = 0; it < 2; ++it) {
        int t = tid + it * NTHREADS;
        float4 kv = kg[t];
        ulonglong2 lo, hi;
        lo.x = pk2(kv.x, kv.x); lo.y = pk2(kv.y, kv.y);
        hi.x = pk2(kv.z, kv.z); hi.y = pk2(kv.w, kv.w);
        kdup2[t * 2]     = lo;
        kdup2[t * 2 + 1] = hi;
    }
    // load + pack q. Thread (i = tid>>5, ln): lane ln owns cols ln+32j;
    // slot 4i+c packs (col ln+64i, col ln+64i+32) component c.
    {
        int i = tid >> 5, ln = tid & 31;
        int m = ln + 64 * i;
        float4 qa = qg[m];
        float4 qb = qg[m + 32];
        ulonglong2 lo, hi;
        lo.x = pk2(qa.x, qb.x);  lo.y = pk2(qa.y, qb.y);   // slots 4i, 4i+1
        hi.x = pk2(qa.z, qb.z);  hi.y = pk2(qa.w, qb.w);   // slots 4i+2, 4i+3
        qp2[(2 * i) * 32 + ln]     = lo;
        qp2[(2 * i + 1) * 32 + ln] = hi;
    }
    for (int i = tid; i < NTOKS; i += NTHREADS) Ash[i] = 0.f;
    __syncthreads();

    const unsigned long long BIAS = pk2(-100.0f, -100.0f);

    unsigned long long A2[8];
    #pragma unroll
    for (int i = 0; i < 8; ++i) A2[i] = 0ull;

    #pragma unroll 1
    for (int rp = 0; rp < 32; ++rp) {
        int n = warp * 64 + rp * 2;
        ulonglong2 kaL = kdup2[n * 2];          // broadcast LDS.128
        ulonglong2 kaH = kdup2[n * 2 + 1];
        ulonglong2 kbL = kdup2[n * 2 + 2];
        ulonglong2 kbH = kdup2[n * 2 + 3];

        // dots with -100 bias folded into the accumulator init; Q from smem
        unsigned long long e0[8], e1[8];
        #pragma unroll
        for (int i = 0; i < 8; ++i) {
            ulonglong2 qA = qp2[(2 * i) * 32 + lane];       // slots 4i, 4i+1
            ulonglong2 qB = qp2[(2 * i + 1) * 32 + lane];   // slots 4i+2, 4i+3
            unsigned long long a  = fma2(qA.x, kaL.x, BIAS);
            unsigned long long bb = fma2(qA.x, kbL.x, BIAS);
            a  = fma2(qA.y, kaL.y, a);  bb = fma2(qA.y, kbL.y, bb);
            a  = fma2(qB.x, kaH.x, a);  bb = fma2(qB.x, kbH.x, bb);
            a  = fma2(qB.y, kaH.y, a);  bb = fma2(qB.y, kbH.y, bb);
            e0[i] = a; e1[i] = bb;
        }

        // row shift = max(rowmax_arg, 0): scalar fmaxf tree seeded with 0 ->
        // all lane values >= 0 -> raw s32 REDUX.MAX == float max (exact).
        float m0 = 0.0f, m1 = 0.0f;
        #pragma unroll
        for (int i = 0; i < 8; ++i) {
            float lo, hi;
            upk2(lo, hi, e0[i]); m0 = fmaxf(m0, fmaxf(lo, hi));
            upk2(lo, hi, e1[i]); m1 = fmaxf(m1, fmaxf(lo, hi));
        }
        m0 = __int_as_float(__reduce_max_sync(0xffffffffu, __float_as_int(m0)));
        m1 = __int_as_float(__reduce_max_sync(0xffffffffu, __float_as_int(m1)));

        // subtract shift (packed), exp2: args <= 0 -> e <= 1 always
        unsigned long long S0 = pk2(-m0, -m0), S1 = pk2(-m1, -m1);
        #pragma unroll
        for (int i = 0; i < 8; ++i) {
            float lo, hi;
            upk2(lo, hi, add2(e0[i], S0));
            e0[i] = pk2(ex2f_fast(lo), ex2f_fast(hi));
            upk2(lo, hi, add2(e1[i], S1));
            e1[i] = pk2(ex2f_fast(lo), ex2f_fast(hi));
        }

        // packed lane-sum trees, both rows' sums ride one f32x2 butterfly
        unsigned long long t0 = add2(add2(add2(e0[0], e0[1]), add2(e0[2], e0[3])),
                                     add2(add2(e0[4], e0[5]), add2(e0[6], e0[7])));
        unsigned long long t1 = add2(add2(add2(e1[0], e1[1]), add2(e1[2], e1[3])),
                                     add2(add2(e1[4], e1[5]), add2(e1[6], e1[7])));
        float lo, hi;
        upk2(lo, hi, t0); float s0 = lo + hi;
        upk2(lo, hi, t1); float s1 = lo + hi;
        unsigned long long s01 = pk2(s0, s1);
        #pragma unroll
        for (int off = 16; off > 0; off >>= 1)
            s01 = add2(s01, __shfl_xor_sync(0xffffffffu, s01, off));
        upk2(s0, s1, s01);

        unsigned long long v0, v1;
        {
            float i0 = rcpf_fast(s0), i1 = rcpf_fast(s1);
            v0 = pk2(i0, i0); v1 = pk2(i1, i1);
        }
        #pragma unroll
        for (int i = 0; i < 8; ++i) {
            A2[i] = fma2(e0[i], v0, A2[i]);
            A2[i] = fma2(e1[i], v1, A2[i]);
        }
    }

    #pragma unroll
    for (int i = 0; i < 8; ++i) {
        float lo, hi;
        upk2(lo, hi, A2[i]);
        atomicAdd(&Ash[lane + 64 * i], lo);
        atomicAdd(&Ash[lane + 64 * i + 32], hi);
    }
    __syncthreads();

    // top-12: JAX order (descending, ties -> lower index)
    if (warp == 0) {
        float av[16];
        #pragma unroll
        for (int j = 0; j < 16; ++j) av[j] = Ash[lane + 32 * j];
        #pragma unroll 1
        for (int t = 0; t < TOPK_N; ++t) {
            float bv = -CUDART_INF_F;
            int   bi = 0x7fffffff;
            #pragma unroll
            for (int j = 0; j < 16; ++j) {
                float v = av[j];
                if (v > bv) { bv = v; bi = lane + 32 * j; }
            }
            unsigned key = fkey(bv);
            unsigned win = __reduce_max_sync(0xffffffffu, key);
            unsigned cand = (key == win) ? (unsigned)bi : 0x7fffffffu;
            int idx = (int)__reduce_min_sync(0xffffffffu, cand);
            if (lane == 0) sel[t] = idx;
            #pragma unroll
            for (int j = 0; j < 16; ++j)
                if (idx == lane + 32 * j) av[j] = -CUDART_INF_F;
        }
    }
    __syncthreads();

    const float4* xb4 = (const float4*)(x + (size_t)b * NTOKS * DIN);
    float4* ob4 = (float4*)(out + (size_t)b * TOPK_N * DIN);
    for (int i = tid; i < TOPK_N * 32; i += NTHREADS) {
        int t  = i >> 5;
        int e4 = i & 31;
        ob4[i] = xb4[sel[t] * 32 + e4];
    }
}

extern "C" void kernel_launch(void* const* d_in, const int* in_sizes, int n_in,
                              void* d_out, int out_size)
{
    const float* x  = (const float*)d_in[0];
    const float* wk = (const float*)d_in[1];
    const float* wq = (const float*)d_in[2];
    float* out = (float*)d_out;
    (void)in_sizes; (void)n_in; (void)out_size;

    dim3 g1(8, NBATCH);
    proj_kernel<<<g1, NTHREADS>>>(x, wk, wq);
    attn_kernel<<<NBATCH, NTHREADS>>>(x, out);
}